// round 11
// baseline (speedup 1.0000x reference)
#include <cuda_runtime.h>
#include <cuda_bf16.h>

#define W_IN 160
#define H_IN 160
#define HW   (H_IN * W_IN)
#define C_IN 256
#define POOLED 7
#define MAXT 5                     // max footprint side (3*sw <= 2.16 => <=5)
#define MAXSTRIDE 25
#define NWARP 8

__device__ __forceinline__ void cp_async4(float* smem_dst, const float* gmem_src) {
    unsigned s = (unsigned)__cvta_generic_to_shared(smem_dst);
    asm volatile("cp.async.ca.shared.global [%0], [%1], 4;\n" :: "r"(s), "l"(gmem_src));
}

__global__ __launch_bounds__(C_IN, 8)
void dcnv2_pool_kernel(const float* __restrict__ inp,
                       const float* __restrict__ rois,
                       const float* __restrict__ offset,
                       float* __restrict__ out,
                       int N)
{
    __shared__ float tile[C_IN * MAXSTRIDE];     // 25.6 KB
    __shared__ float swt[NWARP][12];             // per-warp weights: WX[0..4], WY[5..9]

    const int bin = blockIdx.x;
    const int n   = blockIdx.y;
    const int ph  = bin / POOLED;
    const int pw  = bin % POOLED;
    const int tid = threadIdx.x;
    const int lane = tid & 31;
    const int warp = tid >> 5;

    // ---- ROI geometry (uniform across block; per-thread registers) ----
    const float* roi = rois + n * 5;
    const int   b  = (int)__ldg(&roi[0]);
    const float rsw = rintf(__ldg(&roi[1])) * 0.0625f - 0.5f;
    const float rsh = rintf(__ldg(&roi[2])) * 0.0625f - 0.5f;
    const float rew = (rintf(__ldg(&roi[3])) + 1.0f) * 0.0625f - 0.5f;
    const float reh = (rintf(__ldg(&roi[4])) + 1.0f) * 0.0625f - 0.5f;
    const float rw  = fmaxf(rew - rsw, 0.1f);
    const float rh  = fmaxf(reh - rsh, 0.1f);
    const float bw  = rw * (1.0f / 7.0f);
    const float bh  = rh * (1.0f / 7.0f);
    const float sw  = bw * 0.25f;
    const float sh  = bh * 0.25f;

    const float tx = __ldg(&offset[((n * 2 + 0) * POOLED + ph) * POOLED + pw]) * 0.1f;
    const float ty = __ldg(&offset[((n * 2 + 1) * POOLED + ph) * POOLED + pw]) * 0.1f;

    const float wstart = pw * bw + rsw + tx * rw;
    const float hstart = ph * bh + rsh + ty * rh;

    // ---- exact clipped footprint (x,y monotone in sample index) ----
    const float xcA = fminf(fmaxf(wstart,             0.0f), (float)(W_IN - 1));
    const float xcB = fminf(fmaxf(wstart + 3.0f * sw, 0.0f), (float)(W_IN - 1));
    const float ycA = fminf(fmaxf(hstart,             0.0f), (float)(H_IN - 1));
    const float ycB = fminf(fmaxf(hstart + 3.0f * sh, 0.0f), (float)(H_IN - 1));
    const int xlo = (int)floorf(xcA);
    const int ylo = (int)floorf(ycA);
    const int w   = min((int)ceilf(xcB) - xlo + 1, MAXT);   // 1..5, fully in-image
    const int h   = min((int)ceilf(ycB) - ylo + 1, MAXT);
    const int area   = w * h;                               // <= 25
    const int stride = area | 1;                            // odd -> conflict-free

    // ---- stage footprint with cp.async (warp-local) ----
    {
        const int yy  = lane / w;
        const int xx  = lane - yy * w;
        const int off = (ylo + yy) * W_IN + (xlo + xx);     // in-image by construction
        const float* gp = inp + (size_t)b * (C_IN * HW) + (size_t)(warp * 32) * HW + off;
        float* sp = tile + (warp * 32) * stride + lane;
        if (lane < area) {
            #pragma unroll
            for (int i = 0; i < 32; i++) {
                cp_async4(sp, gp);
                gp += HW;
                sp += stride;
            }
        }
        asm volatile("cp.async.commit_group;\n" ::: "memory");
    }

    // ---- lane-parallel separable weights -> per-warp smem (no atomics) ----
    // Lanes 0..4: WX[lane]; lanes 5..9: WY[lane-5]. cnt via shfl of cval.
    // WX[e] = sum_s okX * hat(xc_s - (xlo+e)); hat(d)=max(0,1-|d|) reproduces
    // floor/ceil bilinear splitting exactly (incl. d==0). cnt = cntX*cntY.
    {
        float wval = 0.0f, cval = 0.0f;
        if (lane < 10) {
            const bool  isX    = lane < 5;
            const int   e      = isX ? lane : lane - 5;
            const float start  = isX ? wstart : hstart;
            const float step   = isX ? sw : sh;
            const float lim    = isX ? (float)W_IN : (float)H_IN;
            const float anchor = (float)((isX ? xlo : ylo) + e);
            #pragma unroll
            for (int s = 0; s < 4; s++) {
                const float v   = start + (float)s * step;
                const float okv = (v >= -0.5f && v <= lim - 0.5f) ? 1.0f : 0.0f;
                const float vc  = fminf(fmaxf(v, 0.0f), lim - 1.0f);
                cval += okv;
                wval += okv * fmaxf(1.0f - fabsf(vc - anchor), 0.0f);
            }
            swt[warp][lane] = wval;
        }
        const float cnt = __shfl_sync(0xffffffffu, cval, 0)
                        * __shfl_sync(0xffffffffu, cval, 5);
        if (lane == 0) swt[warp][10] = fmaxf(cnt, 1.0f);
    }

    asm volatile("cp.async.wait_group 0;\n" ::: "memory");
    __syncwarp();                                // orders STS + staging (warp-local)

    // ---- thread = channel: separable dot, weights via broadcast LDS ----
    const float* tch = tile + tid * stride;
    const float* wv  = swt[warp];
    float acc = 0.0f;
    #pragma unroll
    for (int yy = 0; yy < MAXT; yy++) {
        if (yy < h) {
            float r = 0.0f;
            #pragma unroll
            for (int xx = 0; xx < MAXT; xx++) {
                if (xx < w) r += wv[xx] * tch[yy * w + xx];
            }
            acc += wv[5 + yy] * r;
        }
    }

    out[(((size_t)n * C_IN + tid) * POOLED + ph) * POOLED + pw] = acc / wv[10];
}

extern "C" void kernel_launch(void* const* d_in, const int* in_sizes, int n_in,
                              void* d_out, int out_size)
{
    const float* inp    = (const float*)d_in[0];   // (2, 256, 160, 160) f32
    const float* rois   = (const float*)d_in[1];   // (N, 5) f32
    const float* offset = (const float*)d_in[2];   // (N, 2, 7, 7) f32
    float* out = (float*)d_out;                    // (N, 256, 7, 7) f32

    const int N = in_sizes[1] / 5;

    dim3 grid(POOLED * POOLED, N);                 // 49 x N
    dim3 block(C_IN);
    dcnv2_pool_kernel<<<grid, block>>>(inp, rois, offset, out, N);
}

// round 12
// speedup vs baseline: 1.0887x; 1.0887x over previous
#include <cuda_runtime.h>
#include <cuda_bf16.h>

#define W_IN 160
#define H_IN 160
#define HW   (H_IN * W_IN)
#define C_IN 256
#define POOLED 7
#define MAXT 5                     // max footprint side (3*sw <= 2.16 => <=5)
#define BMAX 2

// 52.4 MB NHWC scratch: g_nhwc[((b*H + y)*W + x)*C + c]
__device__ float g_nhwc[BMAX * HW * C_IN];

// ---------------- kernel 1: NCHW -> NHWC transpose (32x32 smem tiles) --------
__global__ __launch_bounds__(256, 8)
void nchw_to_nhwc_kernel(const float* __restrict__ in)
{
    __shared__ float t[32][33];

    const int xt = blockIdx.x * 32;          // x tile origin (160/32 = 5)
    const int y  = blockIdx.y;               // 0..159
    const int bz = blockIdx.z;               // b*8 + ctile
    const int b  = bz >> 3;
    const int c0 = (bz & 7) * 32;
    const int tx = threadIdx.x;              // 0..31
    const int ty = threadIdx.y;              // 0..7

    // read: (c0+row, y, xt+tx) -- consecutive tx => coalesced
    const float* ip = in + (((size_t)b * C_IN + c0) * H_IN + y) * W_IN + xt;
    #pragma unroll
    for (int i = 0; i < 32; i += 8)
        t[ty + i][tx] = ip[(size_t)(ty + i) * HW + tx];
    __syncthreads();

    // write: (y, xt+row, c0+tx) -- consecutive tx => coalesced
    float* op = g_nhwc + (((size_t)b * H_IN + y) * W_IN + xt) * C_IN + c0;
    #pragma unroll
    for (int i = 0; i < 32; i += 8)
        op[(size_t)(ty + i) * C_IN + tx] = t[tx][ty + i];
}

// ---------------- kernel 2: deformable ROI pool gather on NHWC ---------------
__global__ __launch_bounds__(C_IN, 6)
void dcnv2_pool_kernel(const float* __restrict__ rois,
                       const float* __restrict__ offset,
                       float* __restrict__ out,
                       int N)
{
    const int bin = blockIdx.x;
    const int n   = blockIdx.y;
    const int ph  = bin / POOLED;
    const int pw  = bin % POOLED;
    const int tid = threadIdx.x;             // = channel

    // ---- ROI geometry (uniform across block; per-thread registers) ----
    const float* roi = rois + n * 5;
    const int   b  = (int)__ldg(&roi[0]);
    const float rsw = rintf(__ldg(&roi[1])) * 0.0625f - 0.5f;
    const float rsh = rintf(__ldg(&roi[2])) * 0.0625f - 0.5f;
    const float rew = (rintf(__ldg(&roi[3])) + 1.0f) * 0.0625f - 0.5f;
    const float reh = (rintf(__ldg(&roi[4])) + 1.0f) * 0.0625f - 0.5f;
    const float rw  = fmaxf(rew - rsw, 0.1f);
    const float rh  = fmaxf(reh - rsh, 0.1f);
    const float bw  = rw * (1.0f / 7.0f);
    const float bh  = rh * (1.0f / 7.0f);
    const float sw  = bw * 0.25f;
    const float sh  = bh * 0.25f;

    const float tx = __ldg(&offset[((n * 2 + 0) * POOLED + ph) * POOLED + pw]) * 0.1f;
    const float ty = __ldg(&offset[((n * 2 + 1) * POOLED + ph) * POOLED + pw]) * 0.1f;

    const float wstart = pw * bw + rsw + tx * rw;
    const float hstart = ph * bh + rsh + ty * rh;

    // ---- exact clipped footprint (x,y monotone in sample index) ----
    const float xcA = fminf(fmaxf(wstart,             0.0f), (float)(W_IN - 1));
    const float xcB = fminf(fmaxf(wstart + 3.0f * sw, 0.0f), (float)(W_IN - 1));
    const float ycA = fminf(fmaxf(hstart,             0.0f), (float)(H_IN - 1));
    const float ycB = fminf(fmaxf(hstart + 3.0f * sh, 0.0f), (float)(H_IN - 1));
    const int xlo = (int)floorf(xcA);
    const int ylo = (int)floorf(ycA);
    const int w   = min((int)ceilf(xcB) - xlo + 1, MAXT);   // 1..5, fully in-image
    const int h   = min((int)ceilf(ycB) - ylo + 1, MAXT);

    // ---- separable accumulated weights (R8-proven; registers only) ----
    // wacc[yy][xx] = WY[yy]*WX[xx];  WX[e] = sum_s okX * hat(xc_s - (xlo+e));
    // hat(d)=max(0,1-|d|) reproduces floor/ceil bilinear splitting exactly.
    float WX[MAXT], WY[MAXT];
    #pragma unroll
    for (int e = 0; e < MAXT; e++) { WX[e] = 0.0f; WY[e] = 0.0f; }
    float cntX = 0.0f, cntY = 0.0f;
    #pragma unroll
    for (int s = 0; s < 4; s++) {
        const float x   = wstart + (float)s * sw;
        const float okx = (x >= -0.5f && x <= (float)W_IN - 0.5f) ? 1.0f : 0.0f;
        const float xc  = fminf(fmaxf(x, 0.0f), (float)(W_IN - 1));
        cntX += okx;
        #pragma unroll
        for (int e = 0; e < MAXT; e++)
            WX[e] += okx * fmaxf(1.0f - fabsf(xc - (float)(xlo + e)), 0.0f);

        const float y   = hstart + (float)s * sh;
        const float oky = (y >= -0.5f && y <= (float)H_IN - 0.5f) ? 1.0f : 0.0f;
        const float yc  = fminf(fmaxf(y, 0.0f), (float)(H_IN - 1));
        cntY += oky;
        #pragma unroll
        for (int e = 0; e < MAXT; e++)
            WY[e] += oky * fmaxf(1.0f - fabsf(yc - (float)(ylo + e)), 0.0f);
    }
    const float cnt = cntX * cntY;

    // ---- NHWC gather: lane = channel -> each point is ONE 128B line per warp.
    // All <=25 LDGs are independent (high MLP), no smem, no barriers.
    const float* basep = g_nhwc + (((size_t)b * H_IN + ylo) * W_IN + xlo) * C_IN + tid;
    float acc = 0.0f;
    #pragma unroll
    for (int yy = 0; yy < MAXT; yy++) {
        if (yy < h) {
            float r = 0.0f;
            #pragma unroll
            for (int xx = 0; xx < MAXT; xx++) {
                if (xx < w)
                    r += WX[xx] * __ldg(&basep[(size_t)(yy * W_IN + xx) * C_IN]);
            }
            acc += WY[yy] * r;
        }
    }

    out[(((size_t)n * C_IN + tid) * POOLED + ph) * POOLED + pw] =
        acc / fmaxf(cnt, 1.0f);
}

extern "C" void kernel_launch(void* const* d_in, const int* in_sizes, int n_in,
                              void* d_out, int out_size)
{
    const float* inp    = (const float*)d_in[0];   // (B, 256, 160, 160) f32
    const float* rois   = (const float*)d_in[1];   // (N, 5) f32
    const float* offset = (const float*)d_in[2];   // (N, 2, 7, 7) f32
    float* out = (float*)d_out;                    // (N, 256, 7, 7) f32

    const int B = in_sizes[0] / (C_IN * HW);       // 2
    const int N = in_sizes[1] / 5;

    // kernel 1: layout transform NCHW -> NHWC
    {
        dim3 grid(W_IN / 32, H_IN, B * (C_IN / 32));   // 5 x 160 x 16
        dim3 block(32, 8);
        nchw_to_nhwc_kernel<<<grid, block>>>(inp);
    }
    // kernel 2: gather (same stream -> ordered)
    {
        dim3 grid(POOLED * POOLED, N);                 // 49 x N
        dim3 block(C_IN);
        dcnv2_pool_kernel<<<grid, block>>>(rois, offset, out, N);
    }
}

// round 13
// speedup vs baseline: 1.0948x; 1.0056x over previous
#include <cuda_runtime.h>
#include <cuda_bf16.h>

#define W_IN 160
#define H_IN 160
#define HW   (H_IN * W_IN)
#define C_IN 256
#define POOLED 7
#define MAXT 5                     // max footprint side (3*sw <= 2.16 => <=5)
#define BMAX 2

// 52.4 MB NHWC scratch: g_nhwc[((b*H + y)*W + x)*C + c]
__device__ float g_nhwc[BMAX * HW * C_IN];

// ------------- kernel 1: NCHW -> NHWC transpose, float4 both global sides ----
__global__ __launch_bounds__(256, 8)
void nchw_to_nhwc_kernel(const float* __restrict__ in)
{
    __shared__ float t[32][33];              // [c][x], pad 33 -> conflict-free

    const int xt = blockIdx.x * 32;          // x tile origin (160/32 = 5)
    const int y  = blockIdx.y;               // 0..159
    const int bz = blockIdx.z;               // b*8 + ctile
    const int b  = bz >> 3;
    const int c0 = (bz & 7) * 32;
    const int tx = threadIdx.x;              // 0..7
    const int ty = threadIdx.y;              // 0..31

    // read: channel c0+ty, x = xt + 4*tx .. +3 (LDG.128)
    {
        const float4 v = *(const float4*)(in
            + (((size_t)b * C_IN + c0 + ty) * H_IN + y) * W_IN + xt + 4 * tx);
        t[ty][4 * tx + 0] = v.x;             // banks ty+4tx+k: distinct per warp
        t[ty][4 * tx + 1] = v.y;
        t[ty][4 * tx + 2] = v.z;
        t[ty][4 * tx + 3] = v.w;
    }
    __syncthreads();

    // write: x = xt + ty, channels c0 + 4*tx .. +3 (STG.128)
    {
        float4 v;
        v.x = t[4 * tx + 0][ty];             // banks 4tx+k+ty: distinct per warp
        v.y = t[4 * tx + 1][ty];
        v.z = t[4 * tx + 2][ty];
        v.w = t[4 * tx + 3][ty];
        *(float4*)(g_nhwc
            + (((size_t)b * H_IN + y) * W_IN + xt + ty) * C_IN + c0 + 4 * tx) = v;
    }
}

// ------------- kernel 2: deformable ROI pool gather on NHWC (float4/thread) --
__global__ __launch_bounds__(64)
void dcnv2_pool_kernel(const float* __restrict__ rois,
                       const float* __restrict__ offset,
                       float* __restrict__ out,
                       int N)
{
    const int bin = blockIdx.x;
    const int n   = blockIdx.y;
    const int ph  = bin / POOLED;
    const int pw  = bin % POOLED;
    const int tid = threadIdx.x;             // 0..63 -> channels 4*tid..4*tid+3

    // ---- ROI geometry (uniform across block) ----
    const float* roi = rois + n * 5;
    const int   b  = (int)__ldg(&roi[0]);
    const float rsw = rintf(__ldg(&roi[1])) * 0.0625f - 0.5f;
    const float rsh = rintf(__ldg(&roi[2])) * 0.0625f - 0.5f;
    const float rew = (rintf(__ldg(&roi[3])) + 1.0f) * 0.0625f - 0.5f;
    const float reh = (rintf(__ldg(&roi[4])) + 1.0f) * 0.0625f - 0.5f;
    const float rw  = fmaxf(rew - rsw, 0.1f);
    const float rh  = fmaxf(reh - rsh, 0.1f);
    const float bw  = rw * (1.0f / 7.0f);
    const float bh  = rh * (1.0f / 7.0f);
    const float sw  = bw * 0.25f;
    const float sh  = bh * 0.25f;

    const float tx = __ldg(&offset[((n * 2 + 0) * POOLED + ph) * POOLED + pw]) * 0.1f;
    const float ty = __ldg(&offset[((n * 2 + 1) * POOLED + ph) * POOLED + pw]) * 0.1f;

    const float wstart = pw * bw + rsw + tx * rw;
    const float hstart = ph * bh + rsh + ty * rh;

    // ---- exact clipped footprint (x,y monotone in sample index) ----
    const float xcA = fminf(fmaxf(wstart,             0.0f), (float)(W_IN - 1));
    const float xcB = fminf(fmaxf(wstart + 3.0f * sw, 0.0f), (float)(W_IN - 1));
    const float ycA = fminf(fmaxf(hstart,             0.0f), (float)(H_IN - 1));
    const float ycB = fminf(fmaxf(hstart + 3.0f * sh, 0.0f), (float)(H_IN - 1));
    const int xlo = (int)floorf(xcA);
    const int ylo = (int)floorf(ycA);
    const int w   = min((int)ceilf(xcB) - xlo + 1, MAXT);   // 1..5, fully in-image
    const int h   = min((int)ceilf(ycB) - ylo + 1, MAXT);

    // ---- separable accumulated weights (registers only; proven R8/R12) ----
    float WX[MAXT], WY[MAXT];
    #pragma unroll
    for (int e = 0; e < MAXT; e++) { WX[e] = 0.0f; WY[e] = 0.0f; }
    float cntX = 0.0f, cntY = 0.0f;
    #pragma unroll
    for (int s = 0; s < 4; s++) {
        const float x   = wstart + (float)s * sw;
        const float okx = (x >= -0.5f && x <= (float)W_IN - 0.5f) ? 1.0f : 0.0f;
        const float xc  = fminf(fmaxf(x, 0.0f), (float)(W_IN - 1));
        cntX += okx;
        #pragma unroll
        for (int e = 0; e < MAXT; e++)
            WX[e] += okx * fmaxf(1.0f - fabsf(xc - (float)(xlo + e)), 0.0f);

        const float y   = hstart + (float)s * sh;
        const float oky = (y >= -0.5f && y <= (float)H_IN - 0.5f) ? 1.0f : 0.0f;
        const float yc  = fminf(fmaxf(y, 0.0f), (float)(H_IN - 1));
        cntY += oky;
        #pragma unroll
        for (int e = 0; e < MAXT; e++)
            WY[e] += oky * fmaxf(1.0f - fabsf(yc - (float)(ylo + e)), 0.0f);
    }
    const float inv = 1.0f / fmaxf(cntX * cntY, 1.0f);

    // ---- NHWC gather: thread = 4 consecutive channels (LDG.128) ----
    // Warp covers 256 channels of one point in 8 x 128B lines; all <=25
    // loads independent (high MLP), no smem, no barriers.
    const float4* basep = (const float4*)(g_nhwc
        + (((size_t)b * H_IN + ylo) * W_IN + xlo) * C_IN) + tid;
    float a0 = 0.0f, a1 = 0.0f, a2 = 0.0f, a3 = 0.0f;
    #pragma unroll
    for (int yy = 0; yy < MAXT; yy++) {
        if (yy < h) {
            float r0 = 0.0f, r1 = 0.0f, r2 = 0.0f, r3 = 0.0f;
            #pragma unroll
            for (int xx = 0; xx < MAXT; xx++) {
                if (xx < w) {
                    const float4 v = __ldg(&basep[(size_t)(yy * W_IN + xx) * (C_IN / 4)]);
                    r0 += WX[xx] * v.x;
                    r1 += WX[xx] * v.y;
                    r2 += WX[xx] * v.z;
                    r3 += WX[xx] * v.w;
                }
            }
            a0 += WY[yy] * r0;
            a1 += WY[yy] * r1;
            a2 += WY[yy] * r2;
            a3 += WY[yy] * r3;
        }
    }

    float* op = out + (((size_t)n * C_IN + 4 * tid) * POOLED + ph) * POOLED + pw;
    op[0 * POOLED * POOLED] = a0 * inv;
    op[1 * POOLED * POOLED] = a1 * inv;
    op[2 * POOLED * POOLED] = a2 * inv;
    op[3 * POOLED * POOLED] = a3 * inv;
}

extern "C" void kernel_launch(void* const* d_in, const int* in_sizes, int n_in,
                              void* d_out, int out_size)
{
    const float* inp    = (const float*)d_in[0];   // (B, 256, 160, 160) f32
    const float* rois   = (const float*)d_in[1];   // (N, 5) f32
    const float* offset = (const float*)d_in[2];   // (N, 2, 7, 7) f32
    float* out = (float*)d_out;                    // (N, 256, 7, 7) f32

    const int B = in_sizes[0] / (C_IN * HW);       // 2
    const int N = in_sizes[1] / 5;

    // kernel 1: layout transform NCHW -> NHWC (float4 both sides)
    {
        dim3 grid(W_IN / 32, H_IN, B * (C_IN / 32));   // 5 x 160 x 16
        dim3 block(8, 32);
        nchw_to_nhwc_kernel<<<grid, block>>>(inp);
    }
    // kernel 2: gather (same stream -> ordered after transpose)
    {
        dim3 grid(POOLED * POOLED, N);                 // 49 x N
        dim3 block(64);
        dcnv2_pool_kernel<<<grid, block>>>(rois, offset, out, N);
    }
}

// round 14
// speedup vs baseline: 1.1405x; 1.0417x over previous
#include <cuda_runtime.h>
#include <cuda_bf16.h>

#define W_IN 160
#define H_IN 160
#define HW   (H_IN * W_IN)
#define C_IN 256
#define POOLED 7
#define MAXT 5                     // max footprint side (3*sw <= 2.16 => <=5)
#define BMAX 2

// 52.4 MB NHWC scratch: g_nhwc[((b*H + y)*W + x)*C + c]
__device__ float g_nhwc[BMAX * HW * C_IN];

// ------------- kernel 1: NCHW -> NHWC transpose, 4 y-rows/block, MLP=4 -------
__global__ __launch_bounds__(256, 8)
void nchw_to_nhwc_kernel(const float* __restrict__ in)
{
    __shared__ float t[4][32][33];           // 4 y-planes of [c][x], padded

    const int xt = blockIdx.x * 32;          // x tile origin (160/32 = 5)
    const int y0 = blockIdx.y * 4;           // 4 y rows per block (160/4 = 40)
    const int bz = blockIdx.z;               // b*8 + ctile
    const int b  = bz >> 3;
    const int c0 = (bz & 7) * 32;
    const int tx = threadIdx.x;              // 0..7  (x quad)
    const int ty = threadIdx.y;              // 0..31 (channel)

    // read: channel c0+ty, rows y0..y0+3, x = xt+4tx.. (4 independent LDG.128)
    const float* ip = in + (((size_t)b * C_IN + c0 + ty) * H_IN + y0) * W_IN + xt + 4 * tx;
    float4 v[4];
    #pragma unroll
    for (int j = 0; j < 4; j++)
        v[j] = *(const float4*)(ip + (size_t)j * W_IN);
    #pragma unroll
    for (int j = 0; j < 4; j++) {
        t[j][ty][4 * tx + 0] = v[j].x;
        t[j][ty][4 * tx + 1] = v[j].y;
        t[j][ty][4 * tx + 2] = v[j].z;
        t[j][ty][4 * tx + 3] = v[j].w;
    }
    __syncthreads();

    // write: x = xt+ty, channels c0+4tx.. (4 independent STG.128)
    #pragma unroll
    for (int j = 0; j < 4; j++) {
        float4 o;
        o.x = t[j][4 * tx + 0][ty];
        o.y = t[j][4 * tx + 1][ty];
        o.z = t[j][4 * tx + 2][ty];
        o.w = t[j][4 * tx + 3][ty];
        *(float4*)(g_nhwc
            + (((size_t)b * H_IN + y0 + j) * W_IN + xt + ty) * C_IN + c0 + 4 * tx) = o;
    }
}

// ------------- kernel 2: gather on NHWC; 4 bins per 256-thread block ---------
__global__ __launch_bounds__(256)
void dcnv2_pool_kernel(const float* __restrict__ rois,
                       const float* __restrict__ offset,
                       float* __restrict__ out,
                       int N)
{
    const int group = threadIdx.x >> 6;      // 0..3 -> bin within block
    const int t64   = threadIdx.x & 63;      // 0..63 -> channels 4*t64..
    const int bin   = blockIdx.x * 4 + group;
    if (bin >= POOLED * POOLED) return;      // uniform per 64-thread group
    const int n  = blockIdx.y;
    const int ph = bin / POOLED;
    const int pw = bin % POOLED;

    // ---- ROI geometry (uniform across group) ----
    const float* roi = rois + n * 5;
    const int   b  = (int)__ldg(&roi[0]);
    const float rsw = rintf(__ldg(&roi[1])) * 0.0625f - 0.5f;
    const float rsh = rintf(__ldg(&roi[2])) * 0.0625f - 0.5f;
    const float rew = (rintf(__ldg(&roi[3])) + 1.0f) * 0.0625f - 0.5f;
    const float reh = (rintf(__ldg(&roi[4])) + 1.0f) * 0.0625f - 0.5f;
    const float rw  = fmaxf(rew - rsw, 0.1f);
    const float rh  = fmaxf(reh - rsh, 0.1f);
    const float bw  = rw * (1.0f / 7.0f);
    const float bh  = rh * (1.0f / 7.0f);
    const float sw  = bw * 0.25f;
    const float sh  = bh * 0.25f;

    const float tx = __ldg(&offset[((n * 2 + 0) * POOLED + ph) * POOLED + pw]) * 0.1f;
    const float ty = __ldg(&offset[((n * 2 + 1) * POOLED + ph) * POOLED + pw]) * 0.1f;

    const float wstart = pw * bw + rsw + tx * rw;
    const float hstart = ph * bh + rsh + ty * rh;

    // ---- exact clipped footprint (x,y monotone in sample index) ----
    const float xcA = fminf(fmaxf(wstart,             0.0f), (float)(W_IN - 1));
    const float xcB = fminf(fmaxf(wstart + 3.0f * sw, 0.0f), (float)(W_IN - 1));
    const float ycA = fminf(fmaxf(hstart,             0.0f), (float)(H_IN - 1));
    const float ycB = fminf(fmaxf(hstart + 3.0f * sh, 0.0f), (float)(H_IN - 1));
    const int xlo = (int)floorf(xcA);
    const int ylo = (int)floorf(ycA);
    const int w   = min((int)ceilf(xcB) - xlo + 1, MAXT);   // 1..5, fully in-image
    const int h   = min((int)ceilf(ycB) - ylo + 1, MAXT);

    // ---- separable accumulated weights (registers only; proven) ----
    float WX[MAXT], WY[MAXT];
    #pragma unroll
    for (int e = 0; e < MAXT; e++) { WX[e] = 0.0f; WY[e] = 0.0f; }
    float cntX = 0.0f, cntY = 0.0f;
    #pragma unroll
    for (int s = 0; s < 4; s++) {
        const float x   = wstart + (float)s * sw;
        const float okx = (x >= -0.5f && x <= (float)W_IN - 0.5f) ? 1.0f : 0.0f;
        const float xc  = fminf(fmaxf(x, 0.0f), (float)(W_IN - 1));
        cntX += okx;
        #pragma unroll
        for (int e = 0; e < MAXT; e++)
            WX[e] += okx * fmaxf(1.0f - fabsf(xc - (float)(xlo + e)), 0.0f);

        const float y   = hstart + (float)s * sh;
        const float oky = (y >= -0.5f && y <= (float)H_IN - 0.5f) ? 1.0f : 0.0f;
        const float yc  = fminf(fmaxf(y, 0.0f), (float)(H_IN - 1));
        cntY += oky;
        #pragma unroll
        for (int e = 0; e < MAXT; e++)
            WY[e] += oky * fmaxf(1.0f - fabsf(yc - (float)(ylo + e)), 0.0f);
    }
    const float inv = 1.0f / fmaxf(cntX * cntY, 1.0f);

    // ---- NHWC gather: thread = 4 consecutive channels (LDG.128) ----
    const float4* basep = (const float4*)(g_nhwc
        + (((size_t)b * H_IN + ylo) * W_IN + xlo) * C_IN) + t64;
    float a0 = 0.0f, a1 = 0.0f, a2 = 0.0f, a3 = 0.0f;
    #pragma unroll
    for (int yy = 0; yy < MAXT; yy++) {
        if (yy < h) {
            float r0 = 0.0f, r1 = 0.0f, r2 = 0.0f, r3 = 0.0f;
            #pragma unroll
            for (int xx = 0; xx < MAXT; xx++) {
                if (xx < w) {
                    const float4 v = __ldg(&basep[(size_t)(yy * W_IN + xx) * (C_IN / 4)]);
                    r0 += WX[xx] * v.x;
                    r1 += WX[xx] * v.y;
                    r2 += WX[xx] * v.z;
                    r3 += WX[xx] * v.w;
                }
            }
            a0 += WY[yy] * r0;
            a1 += WY[yy] * r1;
            a2 += WY[yy] * r2;
            a3 += WY[yy] * r3;
        }
    }

    float* op = out + (((size_t)n * C_IN + 4 * t64) * POOLED + ph) * POOLED + pw;
    op[0 * POOLED * POOLED] = a0 * inv;
    op[1 * POOLED * POOLED] = a1 * inv;
    op[2 * POOLED * POOLED] = a2 * inv;
    op[3 * POOLED * POOLED] = a3 * inv;
}

extern "C" void kernel_launch(void* const* d_in, const int* in_sizes, int n_in,
                              void* d_out, int out_size)
{
    const float* inp    = (const float*)d_in[0];   // (B, 256, 160, 160) f32
    const float* rois   = (const float*)d_in[1];   // (N, 5) f32
    const float* offset = (const float*)d_in[2];   // (N, 2, 7, 7) f32
    float* out = (float*)d_out;                    // (N, 256, 7, 7) f32

    const int B = in_sizes[0] / (C_IN * HW);       // 2
    const int N = in_sizes[1] / 5;

    // kernel 1: layout transform NCHW -> NHWC (4 y-rows per block, MLP=4)
    {
        dim3 grid(W_IN / 32, H_IN / 4, B * (C_IN / 32));   // 5 x 40 x 16
        dim3 block(8, 32);
        nchw_to_nhwc_kernel<<<grid, block>>>(inp);
    }
    // kernel 2: gather (same stream -> ordered after transpose)
    {
        dim3 grid((POOLED * POOLED + 3) / 4, N);           // 13 x N
        dim3 block(256);
        dcnv2_pool_kernel<<<grid, block>>>(rois, offset, out, N);
    }
}

// round 15
// speedup vs baseline: 1.4147x; 1.2405x over previous
#include <cuda_runtime.h>
#include <cuda_bf16.h>

#define W_IN 160
#define H_IN 160
#define HW   (H_IN * W_IN)
#define C_IN 256
#define POOLED 7
#define MAXT 5                     // footprint side: always use full 5x5 window
#define BMAX 2

// 52.4 MB NHWC scratch: g_nhwc[((b*H + y)*W + x)*C + c]
__device__ float g_nhwc[BMAX * HW * C_IN];

// ------------- kernel 1: NCHW -> NHWC transpose, 4 y-rows/block, MLP=4 -------
__global__ __launch_bounds__(256, 8)
void nchw_to_nhwc_kernel(const float* __restrict__ in)
{
    __shared__ float t[4][32][33];           // 4 y-planes of [c][x], padded

    const int xt = blockIdx.x * 32;          // x tile origin (160/32 = 5)
    const int y0 = blockIdx.y * 4;           // 4 y rows per block (160/4 = 40)
    const int bz = blockIdx.z;               // b*8 + ctile
    const int b  = bz >> 3;
    const int c0 = (bz & 7) * 32;
    const int tx = threadIdx.x;              // 0..7  (x quad)
    const int ty = threadIdx.y;              // 0..31 (channel)

    const float* ip = in + (((size_t)b * C_IN + c0 + ty) * H_IN + y0) * W_IN + xt + 4 * tx;
    float4 v[4];
    #pragma unroll
    for (int j = 0; j < 4; j++)
        v[j] = *(const float4*)(ip + (size_t)j * W_IN);
    #pragma unroll
    for (int j = 0; j < 4; j++) {
        t[j][ty][4 * tx + 0] = v[j].x;
        t[j][ty][4 * tx + 1] = v[j].y;
        t[j][ty][4 * tx + 2] = v[j].z;
        t[j][ty][4 * tx + 3] = v[j].w;
    }
    __syncthreads();

    #pragma unroll
    for (int j = 0; j < 4; j++) {
        float4 o;
        o.x = t[j][4 * tx + 0][ty];
        o.y = t[j][4 * tx + 1][ty];
        o.z = t[j][4 * tx + 2][ty];
        o.w = t[j][4 * tx + 3][ty];
        *(float4*)(g_nhwc
            + (((size_t)b * H_IN + y0 + j) * W_IN + xt + ty) * C_IN + c0 + 4 * tx) = o;
    }
}

// ------------- kernel 2: BRANCHLESS 5x5 gather on NHWC (float4/thread) -------
// Correctness of branchless form: WX[e]/WY[e] from the hat construction are
// exactly 0 at anchors with no sample support, so summing the full 5x5 window
// equals the exact footprint sum. Window base is clamped so 5x5 is in-image.
__global__ __launch_bounds__(256)
void dcnv2_pool_kernel(const float* __restrict__ rois,
                       const float* __restrict__ offset,
                       float* __restrict__ out,
                       int N)
{
    const int group = threadIdx.x >> 6;      // 0..3 -> bin within block
    const int t64   = threadIdx.x & 63;      // 0..63 -> channels 4*t64..
    const int bin   = blockIdx.x * 4 + group;
    if (bin >= POOLED * POOLED) return;      // uniform per 64-thread group
    const int n  = blockIdx.y;
    const int ph = bin / POOLED;
    const int pw = bin % POOLED;

    // ---- ROI geometry (uniform across group) ----
    const float* roi = rois + n * 5;
    const int   b  = (int)__ldg(&roi[0]);
    const float rsw = rintf(__ldg(&roi[1])) * 0.0625f - 0.5f;
    const float rsh = rintf(__ldg(&roi[2])) * 0.0625f - 0.5f;
    const float rew = (rintf(__ldg(&roi[3])) + 1.0f) * 0.0625f - 0.5f;
    const float reh = (rintf(__ldg(&roi[4])) + 1.0f) * 0.0625f - 0.5f;
    const float rw  = fmaxf(rew - rsw, 0.1f);
    const float rh  = fmaxf(reh - rsh, 0.1f);
    const float bw  = rw * (1.0f / 7.0f);
    const float bh  = rh * (1.0f / 7.0f);
    const float sw  = bw * 0.25f;
    const float sh  = bh * 0.25f;

    const float tx = __ldg(&offset[((n * 2 + 0) * POOLED + ph) * POOLED + pw]) * 0.1f;
    const float ty = __ldg(&offset[((n * 2 + 1) * POOLED + ph) * POOLED + pw]) * 0.1f;

    const float wstart = pw * bw + rsw + tx * rw;
    const float hstart = ph * bh + rsh + ty * rh;

    // ---- 5x5 window base, clamped fully in-image ----
    const float xcA = fminf(fmaxf(wstart, 0.0f), (float)(W_IN - 1));
    const float ycA = fminf(fmaxf(hstart, 0.0f), (float)(H_IN - 1));
    const int xlo = min((int)floorf(xcA), W_IN - MAXT);
    const int ylo = min((int)floorf(ycA), H_IN - MAXT);

    // ---- separable accumulated weights over the 5 anchors (registers only) ----
    float WX[MAXT], WY[MAXT];
    #pragma unroll
    for (int e = 0; e < MAXT; e++) { WX[e] = 0.0f; WY[e] = 0.0f; }
    float cntX = 0.0f, cntY = 0.0f;
    #pragma unroll
    for (int s = 0; s < 4; s++) {
        const float x   = wstart + (float)s * sw;
        const float okx = (x >= -0.5f && x <= (float)W_IN - 0.5f) ? 1.0f : 0.0f;
        const float xc  = fminf(fmaxf(x, 0.0f), (float)(W_IN - 1));
        cntX += okx;
        #pragma unroll
        for (int e = 0; e < MAXT; e++)
            WX[e] += okx * fmaxf(1.0f - fabsf(xc - (float)(xlo + e)), 0.0f);

        const float y   = hstart + (float)s * sh;
        const float oky = (y >= -0.5f && y <= (float)H_IN - 0.5f) ? 1.0f : 0.0f;
        const float yc  = fminf(fmaxf(y, 0.0f), (float)(H_IN - 1));
        cntY += oky;
        #pragma unroll
        for (int e = 0; e < MAXT; e++)
            WY[e] += oky * fmaxf(1.0f - fabsf(yc - (float)(ylo + e)), 0.0f);
    }
    const float inv = 1.0f / fmaxf(cntX * cntY, 1.0f);

    // ---- branchless gather: 25 independent LDG.128, then weighted reduce ----
    const float4* basep = (const float4*)(g_nhwc
        + (((size_t)b * H_IN + ylo) * W_IN + xlo) * C_IN) + t64;
    float a0 = 0.0f, a1 = 0.0f, a2 = 0.0f, a3 = 0.0f;
    #pragma unroll
    for (int yy = 0; yy < MAXT; yy++) {
        float r0 = 0.0f, r1 = 0.0f, r2 = 0.0f, r3 = 0.0f;
        #pragma unroll
        for (int xx = 0; xx < MAXT; xx++) {
            const float4 v = __ldg(&basep[(size_t)(yy * W_IN + xx) * (C_IN / 4)]);
            r0 += WX[xx] * v.x;
            r1 += WX[xx] * v.y;
            r2 += WX[xx] * v.z;
            r3 += WX[xx] * v.w;
        }
        a0 += WY[yy] * r0;
        a1 += WY[yy] * r1;
        a2 += WY[yy] * r2;
        a3 += WY[yy] * r3;
    }

    float* op = out + (((size_t)n * C_IN + 4 * t64) * POOLED + ph) * POOLED + pw;
    op[0 * POOLED * POOLED] = a0 * inv;
    op[1 * POOLED * POOLED] = a1 * inv;
    op[2 * POOLED * POOLED] = a2 * inv;
    op[3 * POOLED * POOLED] = a3 * inv;
}

extern "C" void kernel_launch(void* const* d_in, const int* in_sizes, int n_in,
                              void* d_out, int out_size)
{
    const float* inp    = (const float*)d_in[0];   // (B, 256, 160, 160) f32
    const float* rois   = (const float*)d_in[1];   // (N, 5) f32
    const float* offset = (const float*)d_in[2];   // (N, 2, 7, 7) f32
    float* out = (float*)d_out;                    // (N, 256, 7, 7) f32

    const int B = in_sizes[0] / (C_IN * HW);       // 2
    const int N = in_sizes[1] / 5;

    // kernel 1: layout transform NCHW -> NHWC
    {
        dim3 grid(W_IN / 32, H_IN / 4, B * (C_IN / 32));   // 5 x 40 x 16
        dim3 block(8, 32);
        nchw_to_nhwc_kernel<<<grid, block>>>(inp);
    }
    // kernel 2: branchless gather (same stream -> ordered after transpose)
    {
        dim3 grid((POOLED * POOLED + 3) / 4, N);           // 13 x N
        dim3 block(256);
        dcnv2_pool_kernel<<<grid, block>>>(rois, offset, out, N);
    }
}

// round 16
// speedup vs baseline: 1.4990x; 1.0596x over previous
#include <cuda_runtime.h>
#include <cuda_bf16.h>

#define W_IN 160
#define H_IN 160
#define HW   (H_IN * W_IN)
#define C_IN 256
#define POOLED 7
#define MAXT 5                     // footprint side: full 5x5 window, weights 0-padded
#define BMAX 2

// 52.4 MB NHWC scratch: g_nhwc[((b*H + y)*W + x)*C + c]
__device__ float g_nhwc[BMAX * HW * C_IN];

// ------------- kernel 1: NCHW -> NHWC transpose, 4 y-rows/block, MLP=4 -------
__global__ __launch_bounds__(256, 8)
void nchw_to_nhwc_kernel(const float* __restrict__ in)
{
    __shared__ float t[4][32][33];           // 4 y-planes of [c][x], padded

    const int xt = blockIdx.x * 32;          // x tile origin (160/32 = 5)
    const int y0 = blockIdx.y * 4;           // 4 y rows per block (160/4 = 40)
    const int bz = blockIdx.z;               // b*8 + ctile
    const int b  = bz >> 3;
    const int c0 = (bz & 7) * 32;
    const int tx = threadIdx.x;              // 0..7  (x quad)
    const int ty = threadIdx.y;              // 0..31 (channel)

    const float* ip = in + (((size_t)b * C_IN + c0 + ty) * H_IN + y0) * W_IN + xt + 4 * tx;
    float4 v[4];
    #pragma unroll
    for (int j = 0; j < 4; j++)
        v[j] = *(const float4*)(ip + (size_t)j * W_IN);
    #pragma unroll
    for (int j = 0; j < 4; j++) {
        t[j][ty][4 * tx + 0] = v[j].x;
        t[j][ty][4 * tx + 1] = v[j].y;
        t[j][ty][4 * tx + 2] = v[j].z;
        t[j][ty][4 * tx + 3] = v[j].w;
    }
    __syncthreads();

    #pragma unroll
    for (int j = 0; j < 4; j++) {
        float4 o;
        o.x = t[j][4 * tx + 0][ty];
        o.y = t[j][4 * tx + 1][ty];
        o.z = t[j][4 * tx + 2][ty];
        o.w = t[j][4 * tx + 3][ty];
        *(float4*)(g_nhwc
            + (((size_t)b * H_IN + y0 + j) * W_IN + xt + ty) * C_IN + c0 + 4 * tx) = o;
    }
}

// ------- kernel 2: predicated branchless 5x5 gather on NHWC (float4/thread) --
// Weights at anchors without sample support are exactly 0 (hat construction),
// so the 5x5 weighted sum equals the exact footprint sum. Loads whose weight
// product is 0 are PREDICATED OFF (uniform @P LDG -> no transaction, no branch).
__global__ __launch_bounds__(256, 6)
void dcnv2_pool_kernel(const float* __restrict__ rois,
                       const float* __restrict__ offset,
                       float* __restrict__ out,
                       int N)
{
    const int group = threadIdx.x >> 6;      // 0..3 -> bin within block
    const int t64   = threadIdx.x & 63;      // 0..63 -> channels 4*t64..
    const int bin   = blockIdx.x * 4 + group;
    if (bin >= POOLED * POOLED) return;      // uniform per 64-thread group
    const int n  = blockIdx.y;
    const int ph = bin / POOLED;
    const int pw = bin % POOLED;

    // ---- ROI geometry (uniform across group) ----
    const float* roi = rois + n * 5;
    const int   b  = (int)__ldg(&roi[0]);
    const float rsw = rintf(__ldg(&roi[1])) * 0.0625f - 0.5f;
    const float rsh = rintf(__ldg(&roi[2])) * 0.0625f - 0.5f;
    const float rew = (rintf(__ldg(&roi[3])) + 1.0f) * 0.0625f - 0.5f;
    const float reh = (rintf(__ldg(&roi[4])) + 1.0f) * 0.0625f - 0.5f;
    const float rw  = fmaxf(rew - rsw, 0.1f);
    const float rh  = fmaxf(reh - rsh, 0.1f);
    const float bw  = rw * (1.0f / 7.0f);
    const float bh  = rh * (1.0f / 7.0f);
    const float sw  = bw * 0.25f;
    const float sh  = bh * 0.25f;

    const float tx = __ldg(&offset[((n * 2 + 0) * POOLED + ph) * POOLED + pw]) * 0.1f;
    const float ty = __ldg(&offset[((n * 2 + 1) * POOLED + ph) * POOLED + pw]) * 0.1f;

    const float wstart = pw * bw + rsw + tx * rw;
    const float hstart = ph * bh + rsh + ty * rh;

    // ---- 5x5 window base, clamped fully in-image ----
    const float xcA = fminf(fmaxf(wstart, 0.0f), (float)(W_IN - 1));
    const float ycA = fminf(fmaxf(hstart, 0.0f), (float)(H_IN - 1));
    const int xlo = min((int)floorf(xcA), W_IN - MAXT);
    const int ylo = min((int)floorf(ycA), H_IN - MAXT);

    // ---- separable accumulated weights over the 5 anchors (registers only) ----
    float WX[MAXT], WY[MAXT];
    #pragma unroll
    for (int e = 0; e < MAXT; e++) { WX[e] = 0.0f; WY[e] = 0.0f; }
    float cntX = 0.0f, cntY = 0.0f;
    #pragma unroll
    for (int s = 0; s < 4; s++) {
        const float x   = wstart + (float)s * sw;
        const float okx = (x >= -0.5f && x <= (float)W_IN - 0.5f) ? 1.0f : 0.0f;
        const float xc  = fminf(fmaxf(x, 0.0f), (float)(W_IN - 1));
        cntX += okx;
        #pragma unroll
        for (int e = 0; e < MAXT; e++)
            WX[e] += okx * fmaxf(1.0f - fabsf(xc - (float)(xlo + e)), 0.0f);

        const float y   = hstart + (float)s * sh;
        const float oky = (y >= -0.5f && y <= (float)H_IN - 0.5f) ? 1.0f : 0.0f;
        const float yc  = fminf(fmaxf(y, 0.0f), (float)(H_IN - 1));
        cntY += oky;
        #pragma unroll
        for (int e = 0; e < MAXT; e++)
            WY[e] += oky * fmaxf(1.0f - fabsf(yc - (float)(ylo + e)), 0.0f);
    }
    const float inv = 1.0f / fmaxf(cntX * cntY, 1.0f);

    // ---- uniform nonzero masks (same for all lanes of the group) ----
    bool px[MAXT], py[MAXT];
    #pragma unroll
    for (int e = 0; e < MAXT; e++) { px[e] = (WX[e] != 0.0f); py[e] = (WY[e] != 0.0f); }

    // ---- predicated gather: 25 independent @P LDG.128, ~10-12 actually fetch ----
    const float4* basep = (const float4*)(g_nhwc
        + (((size_t)b * H_IN + ylo) * W_IN + xlo) * C_IN) + t64;
    float a0 = 0.0f, a1 = 0.0f, a2 = 0.0f, a3 = 0.0f;
    #pragma unroll
    for (int yy = 0; yy < MAXT; yy++) {
        float r0 = 0.0f, r1 = 0.0f, r2 = 0.0f, r3 = 0.0f;
        #pragma unroll
        for (int xx = 0; xx < MAXT; xx++) {
            float4 v = make_float4(0.0f, 0.0f, 0.0f, 0.0f);
            if (px[xx] && py[yy])            // uniform -> @P LDG.128, no branch
                v = __ldg(&basep[(size_t)(yy * W_IN + xx) * (C_IN / 4)]);
            r0 += WX[xx] * v.x;
            r1 += WX[xx] * v.y;
            r2 += WX[xx] * v.z;
            r3 += WX[xx] * v.w;
        }
        a0 += WY[yy] * r0;
        a1 += WY[yy] * r1;
        a2 += WY[yy] * r2;
        a3 += WY[yy] * r3;
    }

    float* op = out + (((size_t)n * C_IN + 4 * t64) * POOLED + ph) * POOLED + pw;
    op[0 * POOLED * POOLED] = a0 * inv;
    op[1 * POOLED * POOLED] = a1 * inv;
    op[2 * POOLED * POOLED] = a2 * inv;
    op[3 * POOLED * POOLED] = a3 * inv;
}

extern "C" void kernel_launch(void* const* d_in, const int* in_sizes, int n_in,
                              void* d_out, int out_size)
{
    const float* inp    = (const float*)d_in[0];   // (B, 256, 160, 160) f32
    const float* rois   = (const float*)d_in[1];   // (N, 5) f32
    const float* offset = (const float*)d_in[2];   // (N, 2, 7, 7) f32
    float* out = (float*)d_out;                    // (N, 256, 7, 7) f32

    const int B = in_sizes[0] / (C_IN * HW);       // 2
    const int N = in_sizes[1] / 5;

    // kernel 1: layout transform NCHW -> NHWC
    {
        dim3 grid(W_IN / 32, H_IN / 4, B * (C_IN / 32));   // 5 x 40 x 16
        dim3 block(8, 32);
        nchw_to_nhwc_kernel<<<grid, block>>>(inp);
    }
    // kernel 2: predicated branchless gather (ordered after transpose)
    {
        dim3 grid((POOLED * POOLED + 3) / 4, N);           // 13 x N
        dim3 block(256);
        dcnv2_pool_kernel<<<grid, block>>>(rois, offset, out, N);
    }
}